// round 1
// baseline (speedup 1.0000x reference)
#include <cuda_runtime.h>

// Problem constants
#define NN    4096
#define CIN   256
#define COUT  256
#define NHEAD 4
#define CHEAD 64
#define LALPHA 0.2f

// Scratch (device globals — no allocation allowed)
__device__ float g_h[NN * COUT];        // projected features, [node][256]
__device__ float g_Es[NN * NHEAD];      // exp(e_src)
__device__ float g_Eas[NN * NHEAD];     // exp(alpha * e_src)
__device__ float g_Ed[NN * NHEAD];      // exp(e_dst)
__device__ float g_Ead[NN * NHEAD];     // exp(alpha * e_dst)

// ---------------------------------------------------------------------------
// Kernel A: h = X @ W^T + b    (4096x256x256 fp32 GEMM, both operands K-major)
// CTA tile 128x64, 256 threads, thread tile 8x4, BK=16.
// ---------------------------------------------------------------------------
__global__ __launch_bounds__(256) void k_gemm_h(const float* __restrict__ X,
                                                const float* __restrict__ W,
                                                const float* __restrict__ b) {
    __shared__ float Xs[16][128];
    __shared__ float Ws[16][64];

    const int n0 = blockIdx.x * 128;
    const int o0 = blockIdx.y * 64;
    const int t  = threadIdx.x;

    const int r0 = (t >> 4) * 8;   // 16 row groups of 8
    const int c0 = (t & 15) * 4;   // 16 col groups of 4

    float acc[8][4];
#pragma unroll
    for (int r = 0; r < 8; r++)
#pragma unroll
        for (int c = 0; c < 4; c++) acc[r][c] = 0.0f;

    for (int k0 = 0; k0 < CIN; k0 += 16) {
        __syncthreads();
        // Load X tile (128x16) transposed into Xs[k][row]
#pragma unroll
        for (int it = 0; it < 2; it++) {
            int idx = it * 256 + t;          // 0..511 float4s
            int r  = idx >> 2;
            int k4 = idx & 3;
            float4 v = *(const float4*)&X[(size_t)(n0 + r) * CIN + k0 + k4 * 4];
            Xs[k4 * 4 + 0][r] = v.x;
            Xs[k4 * 4 + 1][r] = v.y;
            Xs[k4 * 4 + 2][r] = v.z;
            Xs[k4 * 4 + 3][r] = v.w;
        }
        // Load W tile (64x16) transposed into Ws[k][o]
        {
            int o  = t >> 2;
            int k4 = t & 3;
            float4 v = *(const float4*)&W[(size_t)(o0 + o) * CIN + k0 + k4 * 4];
            Ws[k4 * 4 + 0][o] = v.x;
            Ws[k4 * 4 + 1][o] = v.y;
            Ws[k4 * 4 + 2][o] = v.z;
            Ws[k4 * 4 + 3][o] = v.w;
        }
        __syncthreads();
#pragma unroll
        for (int k = 0; k < 16; k++) {
            float4 x0 = *(float4*)&Xs[k][r0];
            float4 x1 = *(float4*)&Xs[k][r0 + 4];
            float4 wv = *(float4*)&Ws[k][c0];
            float xr[8] = {x0.x, x0.y, x0.z, x0.w, x1.x, x1.y, x1.z, x1.w};
            float wc[4] = {wv.x, wv.y, wv.z, wv.w};
#pragma unroll
            for (int r = 0; r < 8; r++)
#pragma unroll
                for (int c = 0; c < 4; c++) acc[r][c] += xr[r] * wc[c];
        }
    }

    float4 bv = *(const float4*)&b[o0 + c0];
#pragma unroll
    for (int r = 0; r < 8; r++) {
        float4 o;
        o.x = acc[r][0] + bv.x;
        o.y = acc[r][1] + bv.y;
        o.z = acc[r][2] + bv.z;
        o.w = acc[r][3] + bv.w;
        *(float4*)&g_h[(size_t)(n0 + r0 + r) * COUT + o0 + c0] = o;
    }
}

// ---------------------------------------------------------------------------
// Kernel E: per (node, head) attention coefficients, pre-exponentiated.
// e_src = h[i,head,:].a_src, e_dst = h[i,head,:].a_dst
// Store exp(e), exp(alpha*e) so the O(N^2) loop needs no transcendentals.
// ---------------------------------------------------------------------------
__global__ __launch_bounds__(128) void k_edge(const float* __restrict__ a) {
    int g = blockIdx.x * 128 + threadIdx.x;     // 16384 = NN*NHEAD
    if (g >= NN * NHEAD) return;
    int node = g >> 2;
    int head = g & 3;
    const float* hrow = &g_h[(size_t)node * COUT + head * CHEAD];
    const float* asrc = &a[head * 2 * CHEAD];
    const float* adst = asrc + CHEAD;
    float s = 0.0f, d = 0.0f;
#pragma unroll
    for (int c = 0; c < CHEAD; c += 4) {
        float4 hv = *(const float4*)&hrow[c];
        float4 av = *(const float4*)&asrc[c];
        float4 dv = *(const float4*)&adst[c];
        s += hv.x * av.x + hv.y * av.y + hv.z * av.z + hv.w * av.w;
        d += hv.x * dv.x + hv.y * dv.y + hv.z * dv.z + hv.w * dv.w;
    }
    g_Es[g]  = expf(s);
    g_Eas[g] = expf(LALPHA * s);
    g_Ed[g]  = expf(d);
    g_Ead[g] = expf(LALPHA * d);
}

// ---------------------------------------------------------------------------
// Kernel B: fused masked softmax + probs@h.
// Per CTA: 16 query rows (all 4 heads), loop over j in tiles of 32:
//   w[i,j,h] = adj ? ( Es*Ed > 1 ? Es*Ed : Eas*Ead ) : 0
//   acc[i,:]  += w[i,j,head(col)] * h[j,:]
//   den[i,h]  += w
// Normalize at the end.  128 threads, thread tile 4 rows x 8 cols.
// ---------------------------------------------------------------------------
#define ITILE 16
#define JTILE 32

__global__ __launch_bounds__(128) void k_attn(const int* __restrict__ adj,
                                              float* __restrict__ out) {
    __shared__ float sh_h[JTILE][COUT];          // 32 KB
    __shared__ float sh_w[JTILE][NHEAD][ITILE];  // 8 KB
    __shared__ float sh_Ed[JTILE][NHEAD];
    __shared__ float sh_Ead[JTILE][NHEAD];
    __shared__ float sh_Es[ITILE][NHEAD];
    __shared__ float sh_Eas[ITILE][NHEAD];
    __shared__ float sh_den[ITILE][NHEAD];

    const int i0 = blockIdx.x * ITILE;
    const int t  = threadIdx.x;

    const int cg   = t & 31;        // 32 col groups of 8
    const int rg   = t >> 5;        // 4 row groups of 4
    const int r0   = rg * 4;
    const int head = cg >> 3;       // 8 col groups per head
    const int col  = cg * 8;
    const bool den_thread = ((cg & 7) == 0);

    if (t < ITILE * NHEAD) {
        int ii = t >> 2, h = t & 3;
        sh_Es[ii][h]  = g_Es[(i0 + ii) * NHEAD + h];
        sh_Eas[ii][h] = g_Eas[(i0 + ii) * NHEAD + h];
    }

    float acc[4][8];
#pragma unroll
    for (int r = 0; r < 4; r++)
#pragma unroll
        for (int c = 0; c < 8; c++) acc[r][c] = 0.0f;
    float dacc[4] = {0.0f, 0.0f, 0.0f, 0.0f};

    for (int j0 = 0; j0 < NN; j0 += JTILE) {
        __syncthreads();
        // Load h tile: 32x256 floats = 2048 float4 / 128 threads
#pragma unroll
        for (int it = 0; it < 16; it++) {
            int idx = it * 128 + t;
            int r  = idx >> 6;
            int c4 = idx & 63;
            *(float4*)&sh_h[r][c4 * 4] =
                *(const float4*)&g_h[(size_t)(j0 + r) * COUT + c4 * 4];
        }
        // Load dst-side exp tables: 128 values each
        {
            int jj = t >> 2, h = t & 3;
            sh_Ed[jj][h]  = g_Ed[(j0 + jj) * NHEAD + h];
            sh_Ead[jj][h] = g_Ead[(j0 + jj) * NHEAD + h];
        }
        __syncthreads();
        // Compute w tile: 512 (i,j) pairs, 4 heads each
#pragma unroll
        for (int k = 0; k < 4; k++) {
            int idx = k * 128 + t;
            int jj = idx & (JTILE - 1);
            int ii = idx >> 5;
            int m = adj[(size_t)(i0 + ii) * NN + j0 + jj];
#pragma unroll
            for (int h = 0; h < NHEAD; h++) {
                float wp = sh_Es[ii][h] * sh_Ed[jj][h];   // exp(s+d)
                float wn = sh_Eas[ii][h] * sh_Ead[jj][h]; // exp(alpha(s+d))
                float w = (wp > 1.0f) ? wp : wn;          // sign(s+d) via wp>1
                sh_w[jj][h][ii] = (m == 1) ? w : 0.0f;
            }
        }
        __syncthreads();
        // GEMM micro-kernel
#pragma unroll 4
        for (int jj = 0; jj < JTILE; jj++) {
            float4 wv = *(float4*)&sh_w[jj][head][r0];
            float4 h0 = *(float4*)&sh_h[jj][col];
            float4 h1 = *(float4*)&sh_h[jj][col + 4];
            float hv[8] = {h0.x, h0.y, h0.z, h0.w, h1.x, h1.y, h1.z, h1.w};
            float wr[4] = {wv.x, wv.y, wv.z, wv.w};
#pragma unroll
            for (int r = 0; r < 4; r++)
#pragma unroll
                for (int c = 0; c < 8; c++) acc[r][c] += wr[r] * hv[c];
            if (den_thread) {
                dacc[0] += wv.x; dacc[1] += wv.y;
                dacc[2] += wv.z; dacc[3] += wv.w;
            }
        }
    }

    if (den_thread) {
#pragma unroll
        for (int r = 0; r < 4; r++) sh_den[r0 + r][head] = dacc[r];
    }
    __syncthreads();

#pragma unroll
    for (int r = 0; r < 4; r++) {
        float rinv = 1.0f / sh_den[r0 + r][head];
        float4 o0, o1;
        o0.x = acc[r][0] * rinv; o0.y = acc[r][1] * rinv;
        o0.z = acc[r][2] * rinv; o0.w = acc[r][3] * rinv;
        o1.x = acc[r][4] * rinv; o1.y = acc[r][5] * rinv;
        o1.z = acc[r][6] * rinv; o1.w = acc[r][7] * rinv;
        size_t base = (size_t)(i0 + r0 + r) * COUT + col;
        *(float4*)&out[base]     = o0;
        *(float4*)&out[base + 4] = o1;
    }
}

// ---------------------------------------------------------------------------
// Launch
// ---------------------------------------------------------------------------
extern "C" void kernel_launch(void* const* d_in, const int* in_sizes, int n_in,
                              void* d_out, int out_size) {
    const float* X   = (const float*)d_in[0];   // node_feats [4096,256]
    const int*   adj = (const int*)d_in[1];     // adj [1,4096,4096]
    const float* W   = (const float*)d_in[2];   // [256,256]
    const float* b   = (const float*)d_in[3];   // [256]
    const float* a   = (const float*)d_in[4];   // [4,128]
    float* out = (float*)d_out;                 // [1,4096,256]

    k_gemm_h<<<dim3(32, 4), 256>>>(X, W, b);
    k_edge<<<128, 128>>>(a);
    k_attn<<<NN / ITILE, 128>>>(adj, out);
}

// round 2
// speedup vs baseline: 1.0012x; 1.0012x over previous
#include <cuda_runtime.h>

// Problem constants
#define NN    4096
#define CIN   256
#define COUT  256
#define NHEAD 4
#define CHEAD 64
#define LALPHA 0.2f

// Scratch (device globals — no allocation allowed)
__device__ float g_h[NN * COUT];        // projected features, [node][256]
__device__ float g_Es[NN * NHEAD];      // exp(e_src)
__device__ float g_Eas[NN * NHEAD];     // exp(alpha * e_src)
__device__ float g_Ed[NN * NHEAD];      // exp(e_dst)
__device__ float g_Ead[NN * NHEAD];     // exp(alpha * e_dst)

// ---------------------------------------------------------------------------
// Kernel A: h = X @ W^T + b    (4096x256x256 fp32 GEMM, both operands K-major)
// CTA tile 128x64, 256 threads, thread tile 8x4, BK=16.
// ---------------------------------------------------------------------------
__global__ __launch_bounds__(256) void k_gemm_h(const float* __restrict__ X,
                                                const float* __restrict__ W,
                                                const float* __restrict__ b) {
    __shared__ float Xs[16][128];
    __shared__ float Ws[16][64];

    const int n0 = blockIdx.x * 128;
    const int o0 = blockIdx.y * 64;
    const int t  = threadIdx.x;

    const int r0 = (t >> 4) * 8;   // 16 row groups of 8
    const int c0 = (t & 15) * 4;   // 16 col groups of 4

    float acc[8][4];
#pragma unroll
    for (int r = 0; r < 8; r++)
#pragma unroll
        for (int c = 0; c < 4; c++) acc[r][c] = 0.0f;

    for (int k0 = 0; k0 < CIN; k0 += 16) {
        __syncthreads();
        // Load X tile (128x16) transposed into Xs[k][row]
#pragma unroll
        for (int it = 0; it < 2; it++) {
            int idx = it * 256 + t;          // 0..511 float4s
            int r  = idx >> 2;
            int k4 = idx & 3;
            float4 v = *(const float4*)&X[(size_t)(n0 + r) * CIN + k0 + k4 * 4];
            Xs[k4 * 4 + 0][r] = v.x;
            Xs[k4 * 4 + 1][r] = v.y;
            Xs[k4 * 4 + 2][r] = v.z;
            Xs[k4 * 4 + 3][r] = v.w;
        }
        // Load W tile (64x16) transposed into Ws[k][o]
        {
            int o  = t >> 2;
            int k4 = t & 3;
            float4 v = *(const float4*)&W[(size_t)(o0 + o) * CIN + k0 + k4 * 4];
            Ws[k4 * 4 + 0][o] = v.x;
            Ws[k4 * 4 + 1][o] = v.y;
            Ws[k4 * 4 + 2][o] = v.z;
            Ws[k4 * 4 + 3][o] = v.w;
        }
        __syncthreads();
#pragma unroll
        for (int k = 0; k < 16; k++) {
            float4 x0 = *(float4*)&Xs[k][r0];
            float4 x1 = *(float4*)&Xs[k][r0 + 4];
            float4 wv = *(float4*)&Ws[k][c0];
            float xr[8] = {x0.x, x0.y, x0.z, x0.w, x1.x, x1.y, x1.z, x1.w};
            float wc[4] = {wv.x, wv.y, wv.z, wv.w};
#pragma unroll
            for (int r = 0; r < 8; r++)
#pragma unroll
                for (int c = 0; c < 4; c++) acc[r][c] += xr[r] * wc[c];
        }
    }

    float4 bv = *(const float4*)&b[o0 + c0];
#pragma unroll
    for (int r = 0; r < 8; r++) {
        float4 o;
        o.x = acc[r][0] + bv.x;
        o.y = acc[r][1] + bv.y;
        o.z = acc[r][2] + bv.z;
        o.w = acc[r][3] + bv.w;
        *(float4*)&g_h[(size_t)(n0 + r0 + r) * COUT + o0 + c0] = o;
    }
}

// ---------------------------------------------------------------------------
// Kernel E: per (node, head) attention coefficients, pre-exponentiated.
// e_src = h[i,head,:].a_src, e_dst = h[i,head,:].a_dst
// Store exp(e), exp(alpha*e) so the O(N^2) loop needs no transcendentals.
// ---------------------------------------------------------------------------
__global__ __launch_bounds__(128) void k_edge(const float* __restrict__ a) {
    int g = blockIdx.x * 128 + threadIdx.x;     // 16384 = NN*NHEAD
    if (g >= NN * NHEAD) return;
    int node = g >> 2;
    int head = g & 3;
    const float* hrow = &g_h[(size_t)node * COUT + head * CHEAD];
    const float* asrc = &a[head * 2 * CHEAD];
    const float* adst = asrc + CHEAD;
    float s = 0.0f, d = 0.0f;
#pragma unroll
    for (int c = 0; c < CHEAD; c += 4) {
        float4 hv = *(const float4*)&hrow[c];
        float4 av = *(const float4*)&asrc[c];
        float4 dv = *(const float4*)&adst[c];
        s += hv.x * av.x + hv.y * av.y + hv.z * av.z + hv.w * av.w;
        d += hv.x * dv.x + hv.y * dv.y + hv.z * dv.z + hv.w * dv.w;
    }
    g_Es[g]  = expf(s);
    g_Eas[g] = expf(LALPHA * s);
    g_Ed[g]  = expf(d);
    g_Ead[g] = expf(LALPHA * d);
}

// ---------------------------------------------------------------------------
// Kernel B: fused masked softmax + probs@h.
// Per CTA: 16 query rows (all 4 heads), loop over j in tiles of 32:
//   w[i,j,h] = adj ? ( Es*Ed > 1 ? Es*Ed : Eas*Ead ) : 0
//   acc[i,:]  += w[i,j,head(col)] * h[j,:]
//   den[i,h]  += w
// Normalize at the end.  128 threads, thread tile 4 rows x 8 cols.
// ---------------------------------------------------------------------------
#define ITILE 16
#define JTILE 32

__global__ __launch_bounds__(128) void k_attn(const int* __restrict__ adj,
                                              float* __restrict__ out) {
    __shared__ float sh_h[JTILE][COUT];          // 32 KB
    __shared__ float sh_w[JTILE][NHEAD][ITILE];  // 8 KB
    __shared__ float sh_Ed[JTILE][NHEAD];
    __shared__ float sh_Ead[JTILE][NHEAD];
    __shared__ float sh_Es[ITILE][NHEAD];
    __shared__ float sh_Eas[ITILE][NHEAD];
    __shared__ float sh_den[ITILE][NHEAD];

    const int i0 = blockIdx.x * ITILE;
    const int t  = threadIdx.x;

    const int cg   = t & 31;        // 32 col groups of 8
    const int rg   = t >> 5;        // 4 row groups of 4
    const int r0   = rg * 4;
    const int head = cg >> 3;       // 8 col groups per head
    const int col  = cg * 8;
    const bool den_thread = ((cg & 7) == 0);

    if (t < ITILE * NHEAD) {
        int ii = t >> 2, h = t & 3;
        sh_Es[ii][h]  = g_Es[(i0 + ii) * NHEAD + h];
        sh_Eas[ii][h] = g_Eas[(i0 + ii) * NHEAD + h];
    }

    float acc[4][8];
#pragma unroll
    for (int r = 0; r < 4; r++)
#pragma unroll
        for (int c = 0; c < 8; c++) acc[r][c] = 0.0f;
    float dacc[4] = {0.0f, 0.0f, 0.0f, 0.0f};

    for (int j0 = 0; j0 < NN; j0 += JTILE) {
        __syncthreads();
        // Load h tile: 32x256 floats = 2048 float4 / 128 threads
#pragma unroll
        for (int it = 0; it < 16; it++) {
            int idx = it * 128 + t;
            int r  = idx >> 6;
            int c4 = idx & 63;
            *(float4*)&sh_h[r][c4 * 4] =
                *(const float4*)&g_h[(size_t)(j0 + r) * COUT + c4 * 4];
        }
        // Load dst-side exp tables: 128 values each
        {
            int jj = t >> 2, h = t & 3;
            sh_Ed[jj][h]  = g_Ed[(j0 + jj) * NHEAD + h];
            sh_Ead[jj][h] = g_Ead[(j0 + jj) * NHEAD + h];
        }
        __syncthreads();
        // Compute w tile: 512 (i,j) pairs, 4 heads each
#pragma unroll
        for (int k = 0; k < 4; k++) {
            int idx = k * 128 + t;
            int jj = idx & (JTILE - 1);
            int ii = idx >> 5;
            int m = adj[(size_t)(i0 + ii) * NN + j0 + jj];
#pragma unroll
            for (int h = 0; h < NHEAD; h++) {
                float wp = sh_Es[ii][h] * sh_Ed[jj][h];   // exp(s+d)
                float wn = sh_Eas[ii][h] * sh_Ead[jj][h]; // exp(alpha(s+d))
                float w = (wp > 1.0f) ? wp : wn;          // sign(s+d) via wp>1
                sh_w[jj][h][ii] = (m == 1) ? w : 0.0f;
            }
        }
        __syncthreads();
        // GEMM micro-kernel
#pragma unroll 4
        for (int jj = 0; jj < JTILE; jj++) {
            float4 wv = *(float4*)&sh_w[jj][head][r0];
            float4 h0 = *(float4*)&sh_h[jj][col];
            float4 h1 = *(float4*)&sh_h[jj][col + 4];
            float hv[8] = {h0.x, h0.y, h0.z, h0.w, h1.x, h1.y, h1.z, h1.w};
            float wr[4] = {wv.x, wv.y, wv.z, wv.w};
#pragma unroll
            for (int r = 0; r < 4; r++)
#pragma unroll
                for (int c = 0; c < 8; c++) acc[r][c] += wr[r] * hv[c];
            if (den_thread) {
                dacc[0] += wv.x; dacc[1] += wv.y;
                dacc[2] += wv.z; dacc[3] += wv.w;
            }
        }
    }

    if (den_thread) {
#pragma unroll
        for (int r = 0; r < 4; r++) sh_den[r0 + r][head] = dacc[r];
    }
    __syncthreads();

#pragma unroll
    for (int r = 0; r < 4; r++) {
        float rinv = 1.0f / sh_den[r0 + r][head];
        float4 o0, o1;
        o0.x = acc[r][0] * rinv; o0.y = acc[r][1] * rinv;
        o0.z = acc[r][2] * rinv; o0.w = acc[r][3] * rinv;
        o1.x = acc[r][4] * rinv; o1.y = acc[r][5] * rinv;
        o1.z = acc[r][6] * rinv; o1.w = acc[r][7] * rinv;
        size_t base = (size_t)(i0 + r0 + r) * COUT + col;
        *(float4*)&out[base]     = o0;
        *(float4*)&out[base + 4] = o1;
    }
}

// ---------------------------------------------------------------------------
// Launch
// ---------------------------------------------------------------------------
extern "C" void kernel_launch(void* const* d_in, const int* in_sizes, int n_in,
                              void* d_out, int out_size) {
    const float* X   = (const float*)d_in[0];   // node_feats [4096,256]
    const int*   adj = (const int*)d_in[1];     // adj [1,4096,4096]
    const float* W   = (const float*)d_in[2];   // [256,256]
    const float* b   = (const float*)d_in[3];   // [256]
    const float* a   = (const float*)d_in[4];   // [4,128]
    float* out = (float*)d_out;                 // [1,4096,256]

    k_gemm_h<<<dim3(32, 4), 256>>>(X, W, b);
    k_edge<<<128, 128>>>(a);
    k_attn<<<NN / ITILE, 128>>>(adj, out);
}

// round 4
// speedup vs baseline: 3.2276x; 3.2238x over previous
#include <cuda_runtime.h>
#include <cuda_bf16.h>
#include <cstdint>

#define NN     4096
#define CIN    256
#define COUT   256
#define NHEAD  4
#define CHEAD  64
#define LALPHA 0.2f
#define NSPLIT 2
#define JCHUNK (NN / NSPLIT)

__device__ float g_h[NN * COUT];
__device__ float g_Es[NN * NHEAD];
__device__ float g_Eas[NN * NHEAD];
__device__ float g_Ed[NN * NHEAD];
__device__ float g_Ead[NN * NHEAD];
__device__ __align__(16) __nv_bfloat16 g_hT[COUT * NN];   // h transposed, bf16
__device__ float g_pnum[NSPLIT * NN * COUT];
__device__ float g_pden[NSPLIT * NN * NHEAD];

// ---------------- Kernel A: h = X @ W^T + b -------------------------------
__global__ __launch_bounds__(256) void k_gemm_h(const float* __restrict__ X,
                                                const float* __restrict__ W,
                                                const float* __restrict__ b) {
    __shared__ float Xs[16][128];
    __shared__ float Ws[16][64];
    const int n0 = blockIdx.x * 128, o0 = blockIdx.y * 64, t = threadIdx.x;
    const int r0 = (t >> 4) * 8, c0 = (t & 15) * 4;
    float acc[8][4];
#pragma unroll
    for (int r = 0; r < 8; r++)
#pragma unroll
        for (int c = 0; c < 4; c++) acc[r][c] = 0.0f;
    for (int k0 = 0; k0 < CIN; k0 += 16) {
        __syncthreads();
#pragma unroll
        for (int it = 0; it < 2; it++) {
            int idx = it * 256 + t, r = idx >> 2, k4 = idx & 3;
            float4 v = *(const float4*)&X[(size_t)(n0 + r) * CIN + k0 + k4 * 4];
            Xs[k4 * 4 + 0][r] = v.x; Xs[k4 * 4 + 1][r] = v.y;
            Xs[k4 * 4 + 2][r] = v.z; Xs[k4 * 4 + 3][r] = v.w;
        }
        {
            int o = t >> 2, k4 = t & 3;
            float4 v = *(const float4*)&W[(size_t)(o0 + o) * CIN + k0 + k4 * 4];
            Ws[k4 * 4 + 0][o] = v.x; Ws[k4 * 4 + 1][o] = v.y;
            Ws[k4 * 4 + 2][o] = v.z; Ws[k4 * 4 + 3][o] = v.w;
        }
        __syncthreads();
#pragma unroll
        for (int k = 0; k < 16; k++) {
            float4 x0 = *(float4*)&Xs[k][r0];
            float4 x1 = *(float4*)&Xs[k][r0 + 4];
            float4 wv = *(float4*)&Ws[k][c0];
            float xr[8] = {x0.x, x0.y, x0.z, x0.w, x1.x, x1.y, x1.z, x1.w};
            float wc[4] = {wv.x, wv.y, wv.z, wv.w};
#pragma unroll
            for (int r = 0; r < 8; r++)
#pragma unroll
                for (int c = 0; c < 4; c++) acc[r][c] += xr[r] * wc[c];
        }
    }
    float4 bv = *(const float4*)&b[o0 + c0];
#pragma unroll
    for (int r = 0; r < 8; r++) {
        float4 o;
        o.x = acc[r][0] + bv.x; o.y = acc[r][1] + bv.y;
        o.z = acc[r][2] + bv.z; o.w = acc[r][3] + bv.w;
        *(float4*)&g_h[(size_t)(n0 + r0 + r) * COUT + o0 + c0] = o;
    }
}

// ---------------- Kernel E: exp tables -------------------------------------
__global__ __launch_bounds__(128) void k_edge(const float* __restrict__ a) {
    int g = blockIdx.x * 128 + threadIdx.x;
    if (g >= NN * NHEAD) return;
    int node = g >> 2, head = g & 3;
    const float* hrow = &g_h[(size_t)node * COUT + head * CHEAD];
    const float* asrc = &a[head * 2 * CHEAD];
    const float* adst = asrc + CHEAD;
    float s = 0.0f, d = 0.0f;
#pragma unroll
    for (int c = 0; c < CHEAD; c += 4) {
        float4 hv = *(const float4*)&hrow[c];
        float4 av = *(const float4*)&asrc[c];
        float4 dv = *(const float4*)&adst[c];
        s += hv.x * av.x + hv.y * av.y + hv.z * av.z + hv.w * av.w;
        d += hv.x * dv.x + hv.y * dv.y + hv.z * dv.z + hv.w * dv.w;
    }
    g_Es[g] = expf(s);  g_Eas[g] = expf(LALPHA * s);
    g_Ed[g] = expf(d);  g_Ead[g] = expf(LALPHA * d);
}

// ---------------- Kernel P: transpose + bf16 -------------------------------
__global__ void k_prep() {
    __shared__ float tile[32][33];
    int j0 = blockIdx.x * 32, c0 = blockIdx.y * 32;
    int tx = threadIdx.x, ty = threadIdx.y;
#pragma unroll
    for (int i = 0; i < 4; i++)
        tile[ty + i * 8][tx] = g_h[(size_t)(j0 + ty + i * 8) * COUT + c0 + tx];
    __syncthreads();
#pragma unroll
    for (int i = 0; i < 4; i++) {
        int c = c0 + ty + i * 8;
        g_hT[(size_t)c * NN + j0 + tx] = __float2bfloat16(tile[tx][ty + i * 8]);
    }
}

// ---------------- mma helpers ----------------------------------------------
__device__ __forceinline__ uint32_t smem_u32(const void* p) {
    uint32_t r;
    asm("{ .reg .u64 t; cvta.to.shared.u64 t, %1; cvt.u32.u64 %0, t; }"
        : "=r"(r) : "l"(p));
    return r;
}
__device__ __forceinline__ void ldm_x4(uint32_t* r, uint32_t a) {
    asm volatile("ldmatrix.sync.aligned.m8n8.x4.shared.b16 {%0,%1,%2,%3}, [%4];"
                 : "=r"(r[0]), "=r"(r[1]), "=r"(r[2]), "=r"(r[3]) : "r"(a));
}
__device__ __forceinline__ void mma_bf16(float* d, const uint32_t* a,
                                         const uint32_t* b) {
    asm volatile(
        "mma.sync.aligned.m16n8k16.row.col.f32.bf16.bf16.f32 "
        "{%0,%1,%2,%3}, {%4,%5,%6,%7}, {%8,%9}, {%0,%1,%2,%3};"
        : "+f"(d[0]), "+f"(d[1]), "+f"(d[2]), "+f"(d[3])
        : "r"(a[0]), "r"(a[1]), "r"(a[2]), "r"(a[3]), "r"(b[0]), "r"(b[1]));
}

// smem layout (bytes)
#define BS_OFF   0        // 4 heads x 64 rows x 256B = 65536
#define WHI_OFF  65536    // 64 x 256B
#define WLO_OFF  81920
#define ADJ_OFF  98304    // 64 rows x 4 u32
#define ED_OFF   99328    // float[4][128]
#define EAD_OFF  101376
#define ESEA_OFF 103424   // float2[4][64]
#define DEN_OFF  105472   // float[64][4]
#define SMEM_DYN 106496

// ---------------- Kernel T: fused attention on mma.sync --------------------
__global__ void __launch_bounds__(256) k_attn_mma(const int* __restrict__ adj) {
    extern __shared__ char Sp[];
    const uint32_t Sb = smem_u32(Sp);
    const int t = threadIdx.x, lane = t & 31, wid = t >> 5;
    const int i0 = blockIdx.x * 64;
    const int split = blockIdx.y;

    float*    shEd   = (float*)(Sp + ED_OFF);
    float*    shEad  = (float*)(Sp + EAD_OFF);
    float2*   shEsEa = (float2*)(Sp + ESEA_OFF);
    uint32_t* adjb   = (uint32_t*)(Sp + ADJ_OFF);
    float*    sden   = (float*)(Sp + DEN_OFF);

    {
        int h = t >> 6, r = t & 63;
        shEsEa[h * 64 + r] = make_float2(g_Es[(size_t)(i0 + r) * NHEAD + h],
                                         g_Eas[(size_t)(i0 + r) * NHEAD + h]);
        sden[t] = 0.0f;
    }

    float acc[NHEAD][4][4];
#pragma unroll
    for (int h = 0; h < NHEAD; h++)
#pragma unroll
        for (int n = 0; n < 4; n++)
#pragma unroll
            for (int k = 0; k < 4; k++) acc[h][n][k] = 0.0f;

    // w-gen mapping: warp owns rows wid*8..+7; lane quad q covers j-subsets
    const int q = lane & 3, rsub = lane >> 2;
    const int wrow = wid * 8 + rsub;
    // mma mapping: warp = (m-tile, n-half)
    const int mi = wid & 3, nj = wid >> 2;
    const int arow = mi * 16 + (lane & 15);
    const int brow0 = nj * 32 + (lane & 7) + ((lane >> 4) << 3);
    const int brow1 = brow0 + 16;

    for (int jt = 0; jt < JCHUNK / 128; jt++) {
        const int j0 = split * JCHUNK + jt * 128;
        __syncthreads();   // prior iteration done reading Bs/adj/tables

        // adjacency -> bitmask (ballot)
        {
            const int jloc = t & 127, word = wid & 3, rbase = wid >> 2;
#pragma unroll 4
            for (int itr = 0; itr < 32; itr++) {
                int row = itr * 2 + rbase;
                int v = adj[(size_t)(i0 + row) * NN + j0 + jloc];
                unsigned m = __ballot_sync(0xffffffffu, v == 1);
                if (lane == 0) adjb[row * 4 + word] = m;
            }
        }
        // h tiles for all heads: 256 rows x 128 bf16, swizzled
        {
#pragma unroll
            for (int itb = 0; itb < 16; itb++) {
                int idx = itb * 256 + t;
                int row = idx >> 4, ch = idx & 15;
                uint4 v = *(const uint4*)&g_hT[(size_t)row * NN + j0 + ch * 8];
                *(uint4*)(Sp + BS_OFF + row * 256 + ((ch ^ (row & 7)) << 4)) = v;
            }
        }
        // j-side exp tables
        for (int idx = t; idx < 512; idx += 256) {
            int jj = idx >> 2, h = idx & 3;
            shEd[h * 128 + jj]  = g_Ed[(size_t)(j0 + jj) * NHEAD + h];
            shEad[h * 128 + jj] = g_Ead[(size_t)(j0 + jj) * NHEAD + h];
        }
        __syncthreads();

#pragma unroll
        for (int h = 0; h < NHEAD; h++) {
            // ---- w generation (hi/lo bf16) ----
            {
                float2 es = shEsEa[h * 64 + wrow];
                float dsum = 0.0f;
#pragma unroll
                for (int it2 = 0; it2 < 8; it2++) {
                    int j = q * 4 + it2 * 16;
                    float4 ed = *(float4*)&shEd[h * 128 + j];
                    float4 ea = *(float4*)&shEad[h * 128 + j];
                    uint32_t bits = (adjb[wrow * 4 + (j >> 5)] >> (j & 31)) & 0xFu;
                    float w0 = es.x * ed.x > 1.0f ? es.x * ed.x : es.y * ea.x;
                    float w1 = es.x * ed.y > 1.0f ? es.x * ed.y : es.y * ea.y;
                    float w2 = es.x * ed.z > 1.0f ? es.x * ed.z : es.y * ea.z;
                    float w3 = es.x * ed.w > 1.0f ? es.x * ed.w : es.y * ea.w;
                    w0 = (bits & 1u) ? w0 : 0.0f;
                    w1 = (bits & 2u) ? w1 : 0.0f;
                    w2 = (bits & 4u) ? w2 : 0.0f;
                    w3 = (bits & 8u) ? w3 : 0.0f;
                    dsum += (w0 + w1) + (w2 + w3);
                    uint32_t hp0, hp1;
                    asm("cvt.rn.bf16x2.f32 %0, %1, %2;" : "=r"(hp0) : "f"(w1), "f"(w0));
                    asm("cvt.rn.bf16x2.f32 %0, %1, %2;" : "=r"(hp1) : "f"(w3), "f"(w2));
                    float l0 = w0 - __uint_as_float(hp0 << 16);
                    float l1 = w1 - __uint_as_float(hp0 & 0xffff0000u);
                    float l2 = w2 - __uint_as_float(hp1 << 16);
                    float l3 = w3 - __uint_as_float(hp1 & 0xffff0000u);
                    uint32_t lp0, lp1;
                    asm("cvt.rn.bf16x2.f32 %0, %1, %2;" : "=r"(lp0) : "f"(l1), "f"(l0));
                    asm("cvt.rn.bf16x2.f32 %0, %1, %2;" : "=r"(lp1) : "f"(l3), "f"(l2));
                    int ch = j >> 3;
                    uint32_t off = wrow * 256 + ((ch ^ (wrow & 7)) << 4) + (j & 7) * 2;
                    *(uint2*)(Sp + WHI_OFF + off) = make_uint2(hp0, hp1);
                    *(uint2*)(Sp + WLO_OFF + off) = make_uint2(lp0, lp1);
                }
                dsum += __shfl_xor_sync(0xffffffffu, dsum, 1);
                dsum += __shfl_xor_sync(0xffffffffu, dsum, 2);
                if (q == 0) sden[wrow * 4 + h] += dsum;
            }
            __syncthreads();

            // ---- MMA stage ----
            {
                const uint32_t aBaseHi = Sb + WHI_OFF + arow * 256;
                const uint32_t aBaseLo = Sb + WLO_OFF + arow * 256;
                const uint32_t bBase   = Sb + BS_OFF + h * 16384;
                const int alow = arow & 7;
                const uint32_t b0row = bBase + brow0 * 256;
                const uint32_t b1row = bBase + brow1 * 256;
                const int bl0 = brow0 & 7, bl1 = brow1 & 7;
#pragma unroll
                for (int ks = 0; ks < 8; ks++) {
                    uint32_t ahi[4], alo4[4], bA[4], bB[4];
                    int ach = ks * 2 + (lane >> 4);
                    uint32_t aoff = (uint32_t)((ach ^ alow) << 4);
                    ldm_x4(ahi, aBaseHi + aoff);
                    ldm_x4(alo4, aBaseLo + aoff);
                    int bch = ks * 2 + ((lane >> 3) & 1);
                    ldm_x4(bA, b0row + ((bch ^ bl0) << 4));
                    ldm_x4(bB, b1row + ((bch ^ bl1) << 4));
                    mma_bf16(acc[h][0], ahi, bA);
                    mma_bf16(acc[h][1], ahi, bA + 2);
                    mma_bf16(acc[h][2], ahi, bB);
                    mma_bf16(acc[h][3], ahi, bB + 2);
                    mma_bf16(acc[h][0], alo4, bA);
                    mma_bf16(acc[h][1], alo4, bA + 2);
                    mma_bf16(acc[h][2], alo4, bB);
                    mma_bf16(acc[h][3], alo4, bB + 2);
                }
            }
            __syncthreads();
        }
    }

    // ---- epilogue: write partial num / den ----
    {
        const int r1 = mi * 16 + (lane >> 2), r2 = r1 + 8;
        const int cb = nj * 32 + (lane & 3) * 2;
#pragma unroll
        for (int h = 0; h < NHEAD; h++)
#pragma unroll
            for (int nt = 0; nt < 4; nt++) {
                int c = h * CHEAD + nt * 8 + cb;
                size_t o1 = ((size_t)split * NN + i0 + r1) * COUT + c;
                size_t o2 = ((size_t)split * NN + i0 + r2) * COUT + c;
                *(float2*)&g_pnum[o1] = make_float2(acc[h][nt][0], acc[h][nt][1]);
                *(float2*)&g_pnum[o2] = make_float2(acc[h][nt][2], acc[h][nt][3]);
            }
        g_pden[((size_t)split * NN + i0 + (t >> 2)) * NHEAD + (t & 3)] = sden[t];
    }
}

// ---------------- Kernel F: combine splits + normalize ---------------------
__global__ __launch_bounds__(256) void k_final(float* __restrict__ out) {
    int gid = blockIdx.x * 256 + threadIdx.x;
    int node = gid >> 8, col = gid & 255, h = col >> 6;
    float num = 0.0f, den = 0.0f;
#pragma unroll
    for (int s = 0; s < NSPLIT; s++) {
        num += g_pnum[((size_t)s * NN + node) * COUT + col];
        den += g_pden[((size_t)s * NN + node) * NHEAD + h];
    }
    out[gid] = num / den;
}

// ---------------- Launch ----------------------------------------------------
extern "C" void kernel_launch(void* const* d_in, const int* in_sizes, int n_in,
                              void* d_out, int out_size) {
    const float* X   = (const float*)d_in[0];
    const int*   adj = (const int*)d_in[1];
    const float* W   = (const float*)d_in[2];
    const float* b   = (const float*)d_in[3];
    const float* a   = (const float*)d_in[4];
    float* out = (float*)d_out;

    cudaFuncSetAttribute(k_attn_mma, cudaFuncAttributeMaxDynamicSharedMemorySize,
                         SMEM_DYN);

    k_gemm_h<<<dim3(32, 4), 256>>>(X, W, b);
    k_edge<<<128, 128>>>(a);
    k_prep<<<dim3(NN / 32, COUT / 32), dim3(32, 8)>>>();
    k_attn_mma<<<dim3(NN / 64, NSPLIT), 256, SMEM_DYN>>>(adj);
    k_final<<<NN * COUT / 256, 256>>>(out);
}

// round 5
// speedup vs baseline: 4.3355x; 1.3433x over previous
#include <cuda_runtime.h>
#include <cuda_fp16.h>
#include <cstdint>

#define NN     4096
#define CIN    256
#define COUT   256
#define NHEAD  4
#define CHEAD  64
#define LALPHA 0.2f
#define NSPLIT 4
#define JCHUNK (NN / NSPLIT)
#define SCALEF 0.001953125f   // 2^-9, folded into Es/Eas (cancels in softmax)

__device__ float g_h[NN * COUT];
__device__ float g_Es[NN * NHEAD];
__device__ float g_Eas[NN * NHEAD];
__device__ float g_Ed[NN * NHEAD];
__device__ float g_Ead[NN * NHEAD];
__device__ __align__(16) __half g_hT[COUT * NN];   // h transposed, fp16
__device__ float g_pnum[NSPLIT * NN * COUT];
__device__ float g_pden[NSPLIT * NN * NHEAD];

// ---------------- Kernel A: h = X @ W^T + b -------------------------------
__global__ __launch_bounds__(256) void k_gemm_h(const float* __restrict__ X,
                                                const float* __restrict__ W,
                                                const float* __restrict__ b) {
    __shared__ float Xs[16][128];
    __shared__ float Ws[16][64];
    const int n0 = blockIdx.x * 128, o0 = blockIdx.y * 64, t = threadIdx.x;
    const int r0 = (t >> 4) * 8, c0 = (t & 15) * 4;
    float acc[8][4];
#pragma unroll
    for (int r = 0; r < 8; r++)
#pragma unroll
        for (int c = 0; c < 4; c++) acc[r][c] = 0.0f;
    for (int k0 = 0; k0 < CIN; k0 += 16) {
        __syncthreads();
#pragma unroll
        for (int it = 0; it < 2; it++) {
            int idx = it * 256 + t, r = idx >> 2, k4 = idx & 3;
            float4 v = *(const float4*)&X[(size_t)(n0 + r) * CIN + k0 + k4 * 4];
            Xs[k4 * 4 + 0][r] = v.x; Xs[k4 * 4 + 1][r] = v.y;
            Xs[k4 * 4 + 2][r] = v.z; Xs[k4 * 4 + 3][r] = v.w;
        }
        {
            int o = t >> 2, k4 = t & 3;
            float4 v = *(const float4*)&W[(size_t)(o0 + o) * CIN + k0 + k4 * 4];
            Ws[k4 * 4 + 0][o] = v.x; Ws[k4 * 4 + 1][o] = v.y;
            Ws[k4 * 4 + 2][o] = v.z; Ws[k4 * 4 + 3][o] = v.w;
        }
        __syncthreads();
#pragma unroll
        for (int k = 0; k < 16; k++) {
            float4 x0 = *(float4*)&Xs[k][r0];
            float4 x1 = *(float4*)&Xs[k][r0 + 4];
            float4 wv = *(float4*)&Ws[k][c0];
            float xr[8] = {x0.x, x0.y, x0.z, x0.w, x1.x, x1.y, x1.z, x1.w};
            float wc[4] = {wv.x, wv.y, wv.z, wv.w};
#pragma unroll
            for (int r = 0; r < 8; r++)
#pragma unroll
                for (int c = 0; c < 4; c++) acc[r][c] += xr[r] * wc[c];
        }
    }
    float4 bv = *(const float4*)&b[o0 + c0];
#pragma unroll
    for (int r = 0; r < 8; r++) {
        float4 o;
        o.x = acc[r][0] + bv.x; o.y = acc[r][1] + bv.y;
        o.z = acc[r][2] + bv.z; o.w = acc[r][3] + bv.w;
        *(float4*)&g_h[(size_t)(n0 + r0 + r) * COUT + o0 + c0] = o;
    }
}

// ---------------- Kernel E: exp tables (Es/Eas carry the 2^-9 scale) -------
__global__ __launch_bounds__(128) void k_edge(const float* __restrict__ a) {
    int g = blockIdx.x * 128 + threadIdx.x;
    if (g >= NN * NHEAD) return;
    int node = g >> 2, head = g & 3;
    const float* hrow = &g_h[(size_t)node * COUT + head * CHEAD];
    const float* asrc = &a[head * 2 * CHEAD];
    const float* adst = asrc + CHEAD;
    float s = 0.0f, d = 0.0f;
#pragma unroll
    for (int c = 0; c < CHEAD; c += 4) {
        float4 hv = *(const float4*)&hrow[c];
        float4 av = *(const float4*)&asrc[c];
        float4 dv = *(const float4*)&adst[c];
        s += hv.x * av.x + hv.y * av.y + hv.z * av.z + hv.w * av.w;
        d += hv.x * dv.x + hv.y * dv.y + hv.z * dv.z + hv.w * dv.w;
    }
    g_Es[g] = expf(s) * SCALEF;  g_Eas[g] = expf(LALPHA * s) * SCALEF;
    g_Ed[g] = expf(d);           g_Ead[g] = expf(LALPHA * d);
}

// ---------------- Kernel P: transpose + fp16 -------------------------------
__global__ void k_prep() {
    __shared__ float tile[32][33];
    int j0 = blockIdx.x * 32, c0 = blockIdx.y * 32;
    int tx = threadIdx.x, ty = threadIdx.y;
#pragma unroll
    for (int i = 0; i < 4; i++)
        tile[ty + i * 8][tx] = g_h[(size_t)(j0 + ty + i * 8) * COUT + c0 + tx];
    __syncthreads();
#pragma unroll
    for (int i = 0; i < 4; i++) {
        int c = c0 + ty + i * 8;
        g_hT[(size_t)c * NN + j0 + tx] = __float2half(tile[tx][ty + i * 8]);
    }
}

// ---------------- mma helpers ----------------------------------------------
__device__ __forceinline__ uint32_t smem_u32(const void* p) {
    uint32_t r;
    asm("{ .reg .u64 t; cvta.to.shared.u64 t, %1; cvt.u32.u64 %0, t; }"
        : "=r"(r) : "l"(p));
    return r;
}
__device__ __forceinline__ void ldm_x4(uint32_t* r, uint32_t a) {
    asm volatile("ldmatrix.sync.aligned.m8n8.x4.shared.b16 {%0,%1,%2,%3}, [%4];"
                 : "=r"(r[0]), "=r"(r[1]), "=r"(r[2]), "=r"(r[3]) : "r"(a));
}
__device__ __forceinline__ void mma_f16(float* d, const uint32_t* a,
                                        const uint32_t* b) {
    asm volatile(
        "mma.sync.aligned.m16n8k16.row.col.f32.f16.f16.f32 "
        "{%0,%1,%2,%3}, {%4,%5,%6,%7}, {%8,%9}, {%0,%1,%2,%3};"
        : "+f"(d[0]), "+f"(d[1]), "+f"(d[2]), "+f"(d[3])
        : "r"(a[0]), "r"(a[1]), "r"(a[2]), "r"(a[3]), "r"(b[0]), "r"(b[1]));
}
__device__ __forceinline__ float half_lo_f32(uint32_t p) {
    float f;
    asm("{ .reg .b16 h; mov.b32 {h, _}, %1; cvt.f32.f16 %0, h; }"
        : "=f"(f) : "r"(p));
    return f;
}
__device__ __forceinline__ float half_hi_f32(uint32_t p) {
    float f;
    asm("{ .reg .b16 h; mov.b32 {_, h}, %1; cvt.f32.f16 %0, h; }"
        : "=f"(f) : "r"(p));
    return f;
}

// smem layout (bytes)
#define BS_OFF   0        // 4 heads x 64 rows x 256B = 65536
#define WHI_OFF  65536    // 64 x 256B
#define WLO_OFF  81920
#define ADJ_OFF  98304    // 64 rows x 4 u32
#define ED_OFF   99328    // float[4][128]
#define EAD_OFF  101376
#define ESEA_OFF 103424   // float2[4][64]
#define DEN_OFF  105472   // float[64][4]
#define SMEM_DYN 106496

// ---------------- Kernel T: fused attention on mma.sync --------------------
__global__ void __launch_bounds__(256, 2) k_attn_mma(const int* __restrict__ adj) {
    extern __shared__ char Sp[];
    const uint32_t Sb = smem_u32(Sp);
    const int t = threadIdx.x, lane = t & 31, wid = t >> 5;
    const int i0 = blockIdx.x * 64;
    const int split = blockIdx.y;

    float*    shEd   = (float*)(Sp + ED_OFF);
    float*    shEad  = (float*)(Sp + EAD_OFF);
    float2*   shEsEa = (float2*)(Sp + ESEA_OFF);
    uint32_t* adjb   = (uint32_t*)(Sp + ADJ_OFF);
    float*    sden   = (float*)(Sp + DEN_OFF);

    {
        int h = t >> 6, r = t & 63;
        shEsEa[h * 64 + r] = make_float2(g_Es[(size_t)(i0 + r) * NHEAD + h],
                                         g_Eas[(size_t)(i0 + r) * NHEAD + h]);
        sden[t] = 0.0f;
    }

    float acc[NHEAD][4][4];
#pragma unroll
    for (int h = 0; h < NHEAD; h++)
#pragma unroll
        for (int n = 0; n < 4; n++)
#pragma unroll
            for (int k = 0; k < 4; k++) acc[h][n][k] = 0.0f;

    const int q = lane & 3, rsub = lane >> 2;
    const int wrow = wid * 8 + rsub;
    const int mi = wid & 3, nj = wid >> 2;
    const int arow = mi * 16 + (lane & 15);
    const int brow0 = nj * 32 + (lane & 7) + ((lane >> 4) << 3);
    const int brow1 = brow0 + 16;

    for (int jt = 0; jt < JCHUNK / 128; jt++) {
        const int j0 = split * JCHUNK + jt * 128;
        __syncthreads();

        // adjacency -> bitmask (ballot)
        {
            const int jloc = t & 127, word = wid & 3, rbase = wid >> 2;
#pragma unroll 4
            for (int itr = 0; itr < 32; itr++) {
                int row = itr * 2 + rbase;
                int v = adj[(size_t)(i0 + row) * NN + j0 + jloc];
                unsigned m = __ballot_sync(0xffffffffu, v == 1);
                if (lane == 0) adjb[row * 4 + word] = m;
            }
        }
        // h tiles for all heads: 256 rows x 128 fp16, swizzled
        {
#pragma unroll
            for (int itb = 0; itb < 16; itb++) {
                int idx = itb * 256 + t;
                int row = idx >> 4, ch = idx & 15;
                uint4 v = *(const uint4*)&g_hT[(size_t)row * NN + j0 + ch * 8];
                *(uint4*)(Sp + BS_OFF + row * 256 + ((ch ^ (row & 7)) << 4)) = v;
            }
        }
        // j-side exp tables
        for (int idx = t; idx < 512; idx += 256) {
            int jj = idx >> 2, h = idx & 3;
            shEd[h * 128 + jj]  = g_Ed[(size_t)(j0 + jj) * NHEAD + h];
            shEad[h * 128 + jj] = g_Ead[(size_t)(j0 + jj) * NHEAD + h];
        }
        __syncthreads();

#pragma unroll
        for (int h = 0; h < NHEAD; h++) {
            // ---- w generation (hi/lo fp16, globally scaled by 2^-9) ----
            {
                float2 es = shEsEa[h * 64 + wrow];
                float dsum = 0.0f;
#pragma unroll
                for (int it2 = 0; it2 < 8; it2++) {
                    int j = q * 4 + it2 * 16;
                    float4 ed = *(float4*)&shEd[h * 128 + j];
                    float4 ea = *(float4*)&shEad[h * 128 + j];
                    uint32_t bits = (adjb[wrow * 4 + (j >> 5)] >> (j & 31)) & 0xFu;
                    float w0 = es.x * ed.x > SCALEF ? es.x * ed.x : es.y * ea.x;
                    float w1 = es.x * ed.y > SCALEF ? es.x * ed.y : es.y * ea.y;
                    float w2 = es.x * ed.z > SCALEF ? es.x * ed.z : es.y * ea.z;
                    float w3 = es.x * ed.w > SCALEF ? es.x * ed.w : es.y * ea.w;
                    w0 = (bits & 1u) ? w0 : 0.0f;
                    w1 = (bits & 2u) ? w1 : 0.0f;
                    w2 = (bits & 4u) ? w2 : 0.0f;
                    w3 = (bits & 8u) ? w3 : 0.0f;
                    dsum += (w0 + w1) + (w2 + w3);
                    uint32_t hp0, hp1;
                    asm("cvt.rn.f16x2.f32 %0, %1, %2;" : "=r"(hp0) : "f"(w1), "f"(w0));
                    asm("cvt.rn.f16x2.f32 %0, %1, %2;" : "=r"(hp1) : "f"(w3), "f"(w2));
                    float l0 = w0 - half_lo_f32(hp0);
                    float l1 = w1 - half_hi_f32(hp0);
                    float l2 = w2 - half_lo_f32(hp1);
                    float l3 = w3 - half_hi_f32(hp1);
                    uint32_t lp0, lp1;
                    asm("cvt.rn.f16x2.f32 %0, %1, %2;" : "=r"(lp0) : "f"(l1), "f"(l0));
                    asm("cvt.rn.f16x2.f32 %0, %1, %2;" : "=r"(lp1) : "f"(l3), "f"(l2));
                    int ch = j >> 3;
                    uint32_t off = wrow * 256 + ((ch ^ (wrow & 7)) << 4) + (j & 7) * 2;
                    *(uint2*)(Sp + WHI_OFF + off) = make_uint2(hp0, hp1);
                    *(uint2*)(Sp + WLO_OFF + off) = make_uint2(lp0, lp1);
                }
                dsum += __shfl_xor_sync(0xffffffffu, dsum, 1);
                dsum += __shfl_xor_sync(0xffffffffu, dsum, 2);
                if (q == 0) sden[wrow * 4 + h] += dsum;
            }
            __syncthreads();

            // ---- MMA stage ----
            {
                const uint32_t aBaseHi = Sb + WHI_OFF + arow * 256;
                const uint32_t aBaseLo = Sb + WLO_OFF + arow * 256;
                const uint32_t bBase   = Sb + BS_OFF + h * 16384;
                const int alow = arow & 7;
                const uint32_t b0row = bBase + brow0 * 256;
                const uint32_t b1row = bBase + brow1 * 256;
                const int bl0 = brow0 & 7, bl1 = brow1 & 7;
#pragma unroll
                for (int ks = 0; ks < 8; ks++) {
                    uint32_t ahi[4], alo4[4], bA[4], bB[4];
                    int ach = ks * 2 + (lane >> 4);
                    uint32_t aoff = (uint32_t)((ach ^ alow) << 4);
                    ldm_x4(ahi, aBaseHi + aoff);
                    ldm_x4(alo4, aBaseLo + aoff);
                    int bch = ks * 2 + ((lane >> 3) & 1);
                    ldm_x4(bA, b0row + ((bch ^ bl0) << 4));
                    ldm_x4(bB, b1row + ((bch ^ bl1) << 4));
                    mma_f16(acc[h][0], ahi, bA);
                    mma_f16(acc[h][1], ahi, bA + 2);
                    mma_f16(acc[h][2], ahi, bB);
                    mma_f16(acc[h][3], ahi, bB + 2);
                    mma_f16(acc[h][0], alo4, bA);
                    mma_f16(acc[h][1], alo4, bA + 2);
                    mma_f16(acc[h][2], alo4, bB);
                    mma_f16(acc[h][3], alo4, bB + 2);
                }
            }
            __syncthreads();
        }
    }

    // ---- epilogue: write partial num / den ----
    {
        const int r1 = mi * 16 + (lane >> 2), r2 = r1 + 8;
        const int cb = nj * 32 + (lane & 3) * 2;
#pragma unroll
        for (int h = 0; h < NHEAD; h++)
#pragma unroll
            for (int nt = 0; nt < 4; nt++) {
                int c = h * CHEAD + nt * 8 + cb;
                size_t o1 = ((size_t)split * NN + i0 + r1) * COUT + c;
                size_t o2 = ((size_t)split * NN + i0 + r2) * COUT + c;
                *(float2*)&g_pnum[o1] = make_float2(acc[h][nt][0], acc[h][nt][1]);
                *(float2*)&g_pnum[o2] = make_float2(acc[h][nt][2], acc[h][nt][3]);
            }
        g_pden[((size_t)split * NN + i0 + (t >> 2)) * NHEAD + (t & 3)] = sden[t];
    }
}

// ---------------- Kernel F: combine splits + normalize ---------------------
__global__ __launch_bounds__(256) void k_final(float* __restrict__ out) {
    int gid = blockIdx.x * 256 + threadIdx.x;
    int node = gid >> 8, col = gid & 255, h = col >> 6;
    float num = 0.0f, den = 0.0f;
#pragma unroll
    for (int s = 0; s < NSPLIT; s++) {
        num += g_pnum[((size_t)s * NN + node) * COUT + col];
        den += g_pden[((size_t)s * NN + node) * NHEAD + h];
    }
    out[gid] = num / den;
}

// ---------------- Launch ----------------------------------------------------
extern "C" void kernel_launch(void* const* d_in, const int* in_sizes, int n_in,
                              void* d_out, int out_size) {
    const float* X   = (const float*)d_in[0];
    const int*   adj = (const int*)d_in[1];
    const float* W   = (const float*)d_in[2];
    const float* b   = (const float*)d_in[3];
    const float* a   = (const float*)d_in[4];
    float* out = (float*)d_out;

    cudaFuncSetAttribute(k_attn_mma, cudaFuncAttributeMaxDynamicSharedMemorySize,
                         SMEM_DYN);

    k_gemm_h<<<dim3(32, 4), 256>>>(X, W, b);
    k_edge<<<128, 128>>>(a);
    k_prep<<<dim3(NN / 32, COUT / 32), dim3(32, 8)>>>();
    k_attn_mma<<<dim3(NN / 64, NSPLIT), 256, SMEM_DYN>>>(adj);
    k_final<<<NN * COUT / 256, 256>>>(out);
}

// round 6
// speedup vs baseline: 5.5006x; 1.2687x over previous
#include <cuda_runtime.h>
#include <cuda_fp16.h>
#include <cstdint>

#define NN     4096
#define CIN    256
#define COUT   256
#define NHEAD  4
#define CHEAD  64
#define LALPHA 0.2f
#define NSPLIT 4
#define JCHUNK (NN / NSPLIT)
#define SCALEF 0.001953125f   // 2^-9 folded into Es/Eas (cancels in softmax)

__device__ float g_h[NN * COUT];
__device__ float g_Es[NN * NHEAD];
__device__ float g_Eas[NN * NHEAD];
__device__ float g_Ed[NN * NHEAD];
__device__ float g_Ead[NN * NHEAD];
__device__ __align__(16) __half g_hT[COUT * NN];      // h transposed, fp16
__device__ uint32_t g_adjp[NN * (NN / 32)];           // packed adjacency, 2MB
__device__ float g_pnum[NSPLIT * NN * COUT];
__device__ float g_pden[NSPLIT * NN * NHEAD];

// ---------------- Kernel A: h = X @ W^T + b  (64x64 tiles, 2 CTA/SM) -------
__global__ __launch_bounds__(256) void k_gemm_h(const float* __restrict__ X,
                                                const float* __restrict__ W,
                                                const float* __restrict__ b) {
    __shared__ float Xs[16][64];
    __shared__ float Ws[16][64];
    const int n0 = blockIdx.x * 64, o0 = blockIdx.y * 64, t = threadIdx.x;
    const int r0 = (t >> 4) * 4, c0 = (t & 15) * 4;
    float acc[4][4];
#pragma unroll
    for (int r = 0; r < 4; r++)
#pragma unroll
        for (int c = 0; c < 4; c++) acc[r][c] = 0.0f;
    for (int k0 = 0; k0 < CIN; k0 += 16) {
        __syncthreads();
        {
            int r = t >> 2, k4 = t & 3;
            float4 v = *(const float4*)&X[(size_t)(n0 + r) * CIN + k0 + k4 * 4];
            Xs[k4 * 4 + 0][r] = v.x; Xs[k4 * 4 + 1][r] = v.y;
            Xs[k4 * 4 + 2][r] = v.z; Xs[k4 * 4 + 3][r] = v.w;
            float4 w = *(const float4*)&W[(size_t)(o0 + r) * CIN + k0 + k4 * 4];
            Ws[k4 * 4 + 0][r] = w.x; Ws[k4 * 4 + 1][r] = w.y;
            Ws[k4 * 4 + 2][r] = w.z; Ws[k4 * 4 + 3][r] = w.w;
        }
        __syncthreads();
#pragma unroll
        for (int k = 0; k < 16; k++) {
            float4 xv = *(float4*)&Xs[k][r0];
            float4 wv = *(float4*)&Ws[k][c0];
            float xr[4] = {xv.x, xv.y, xv.z, xv.w};
            float wc[4] = {wv.x, wv.y, wv.z, wv.w};
#pragma unroll
            for (int r = 0; r < 4; r++)
#pragma unroll
                for (int c = 0; c < 4; c++) acc[r][c] += xr[r] * wc[c];
        }
    }
    float4 bv = *(const float4*)&b[o0 + c0];
#pragma unroll
    for (int r = 0; r < 4; r++) {
        float4 o;
        o.x = acc[r][0] + bv.x; o.y = acc[r][1] + bv.y;
        o.z = acc[r][2] + bv.z; o.w = acc[r][3] + bv.w;
        *(float4*)&g_h[(size_t)(n0 + r0 + r) * COUT + o0 + c0] = o;
    }
}

// ---------------- Kernel E: exp tables (Es/Eas carry the 2^-9 scale) -------
__global__ __launch_bounds__(128) void k_edge(const float* __restrict__ a) {
    int g = blockIdx.x * 128 + threadIdx.x;
    if (g >= NN * NHEAD) return;
    int node = g >> 2, head = g & 3;
    const float* hrow = &g_h[(size_t)node * COUT + head * CHEAD];
    const float* asrc = &a[head * 2 * CHEAD];
    const float* adst = asrc + CHEAD;
    float s = 0.0f, d = 0.0f;
#pragma unroll
    for (int c = 0; c < CHEAD; c += 4) {
        float4 hv = *(const float4*)&hrow[c];
        float4 av = *(const float4*)&asrc[c];
        float4 dv = *(const float4*)&adst[c];
        s += hv.x * av.x + hv.y * av.y + hv.z * av.z + hv.w * av.w;
        d += hv.x * dv.x + hv.y * dv.y + hv.z * dv.z + hv.w * dv.w;
    }
    g_Es[g] = expf(s) * SCALEF;  g_Eas[g] = expf(LALPHA * s) * SCALEF;
    g_Ed[g] = expf(d);           g_Ead[g] = expf(LALPHA * d);
}

// ---------------- Kernel P: transpose + fp16 --------------------------------
__global__ void k_prep() {
    __shared__ float tile[32][33];
    int j0 = blockIdx.x * 32, c0 = blockIdx.y * 32;
    int tx = threadIdx.x, ty = threadIdx.y;
#pragma unroll
    for (int i = 0; i < 4; i++)
        tile[ty + i * 8][tx] = g_h[(size_t)(j0 + ty + i * 8) * COUT + c0 + tx];
    __syncthreads();
#pragma unroll
    for (int i = 0; i < 4; i++) {
        int c = c0 + ty + i * 8;
        g_hT[(size_t)c * NN + j0 + tx] = __float2half(tile[tx][ty + i * 8]);
    }
}

// ---------------- Kernel K: pack adjacency to 1 bit/edge --------------------
__global__ __launch_bounds__(256) void k_pack(const int* __restrict__ adj) {
    int idx = blockIdx.x * 256 + threadIdx.x;    // NN*128 words
    const int4* p = (const int4*)adj + (size_t)idx * 8;
    uint32_t m = 0;
#pragma unroll
    for (int k = 0; k < 8; k++) {
        int4 v = p[k];
        m |= (v.x == 1 ? 1u : 0u) << (k * 4 + 0);
        m |= (v.y == 1 ? 1u : 0u) << (k * 4 + 1);
        m |= (v.z == 1 ? 1u : 0u) << (k * 4 + 2);
        m |= (v.w == 1 ? 1u : 0u) << (k * 4 + 3);
    }
    g_adjp[idx] = m;
}

// ---------------- mma / async helpers ---------------------------------------
__device__ __forceinline__ uint32_t smem_u32(const void* p) {
    uint32_t r;
    asm("{ .reg .u64 t; cvta.to.shared.u64 t, %1; cvt.u32.u64 %0, t; }"
        : "=r"(r) : "l"(p));
    return r;
}
__device__ __forceinline__ void ldm_x4(uint32_t* r, uint32_t a) {
    asm volatile("ldmatrix.sync.aligned.m8n8.x4.shared.b16 {%0,%1,%2,%3}, [%4];"
                 : "=r"(r[0]), "=r"(r[1]), "=r"(r[2]), "=r"(r[3]) : "r"(a));
}
__device__ __forceinline__ void mma_f16(float* d, const uint32_t* a,
                                        const uint32_t* b) {
    asm volatile(
        "mma.sync.aligned.m16n8k16.row.col.f32.f16.f16.f32 "
        "{%0,%1,%2,%3}, {%4,%5,%6,%7}, {%8,%9}, {%0,%1,%2,%3};"
        : "+f"(d[0]), "+f"(d[1]), "+f"(d[2]), "+f"(d[3])
        : "r"(a[0]), "r"(a[1]), "r"(a[2]), "r"(a[3]), "r"(b[0]), "r"(b[1]));
}
#define CP_COMMIT() asm volatile("cp.async.commit_group;")
#define CP_WAIT(n)  asm volatile("cp.async.wait_group %0;" :: "n"(n))

// smem layout (bytes)
#define BB_OFF   0        // 3 x 16384 : B tile (one head, 64 feat x 128 j fp16)
#define WB_OFF   49152    // 3 x 16384 : w tile (64 i x 128 j fp16)
#define ADJ_OFF  98304    // 64 rows x 4 u32
#define ED_OFF   99328    // float[4][128]
#define EAD_OFF  101376
#define ESEA_OFF 103424   // float2[4][64]
#define DEN_OFF  105472   // float[64][4]
#define SMEM_DYN 106496

__device__ __forceinline__ void load_B_tile(uint32_t Sb, int slot, int h,
                                            int j0, int t) {
#pragma unroll
    for (int it = 0; it < 4; it++) {
        int idx = it * 256 + t;
        int row = idx >> 4, ch = idx & 15;
        uint32_t dst = Sb + BB_OFF + slot * 16384 + row * 256 +
                       ((ch ^ (row & 7)) << 4);
        const void* src = &g_hT[(size_t)(h * 64 + row) * NN + j0 + ch * 8];
        asm volatile("cp.async.cg.shared.global [%0], [%1], 16;"
                     :: "r"(dst), "l"(src));
    }
    CP_COMMIT();
}

__device__ __forceinline__ void load_meta(char* Sp, int i0, int j0, int t) {
    uint32_t* adjb = (uint32_t*)(Sp + ADJ_OFF);
    float* shEd  = (float*)(Sp + ED_OFF);
    float* shEad = (float*)(Sp + EAD_OFF);
    adjb[t] = g_adjp[(size_t)(i0 + (t >> 2)) * 128 + (j0 >> 5) + (t & 3)];
#pragma unroll
    for (int k = 0; k < 2; k++) {
        int idx = k * 256 + t;
        int jj = idx >> 2, h = idx & 3;
        shEd[h * 128 + jj]  = g_Ed[(size_t)(j0 + jj) * NHEAD + h];
        shEad[h * 128 + jj] = g_Ead[(size_t)(j0 + jj) * NHEAD + h];
    }
}

__device__ __forceinline__ void wgen_head(char* Sp, int slot, int h,
                                          int wrow, int q) {
    float* shEd  = (float*)(Sp + ED_OFF);
    float* shEad = (float*)(Sp + EAD_OFF);
    float2* shEsEa = (float2*)(Sp + ESEA_OFF);
    float* sden = (float*)(Sp + DEN_OFF);
    char* wb = Sp + WB_OFF + slot * 16384;
    float2 es = shEsEa[h * 64 + wrow];
    uint4 aw = *(uint4*)((uint32_t*)(Sp + ADJ_OFF) + wrow * 4);
    float dsum = 0.0f;
#pragma unroll
    for (int it2 = 0; it2 < 8; it2++) {
        int j = q * 4 + it2 * 16;
        uint32_t word = (it2 < 2) ? aw.x : (it2 < 4) ? aw.y
                       : (it2 < 6) ? aw.z : aw.w;
        uint32_t bits = (word >> (((it2 & 1) << 4) + (q << 2))) & 0xFu;
        float4 ed = *(float4*)&shEd[h * 128 + j];
        float4 ea = *(float4*)&shEad[h * 128 + j];
        float w0 = fmaxf(es.x * ed.x, es.y * ea.x); w0 = (bits & 1u) ? w0 : 0.0f;
        float w1 = fmaxf(es.x * ed.y, es.y * ea.y); w1 = (bits & 2u) ? w1 : 0.0f;
        float w2 = fmaxf(es.x * ed.z, es.y * ea.z); w2 = (bits & 4u) ? w2 : 0.0f;
        float w3 = fmaxf(es.x * ed.w, es.y * ea.w); w3 = (bits & 8u) ? w3 : 0.0f;
        dsum += (w0 + w1) + (w2 + w3);
        uint32_t hp0, hp1;
        asm("cvt.rn.f16x2.f32 %0, %1, %2;" : "=r"(hp0) : "f"(w1), "f"(w0));
        asm("cvt.rn.f16x2.f32 %0, %1, %2;" : "=r"(hp1) : "f"(w3), "f"(w2));
        uint32_t off = wrow * 256 + (((j >> 3) ^ (wrow & 7)) << 4) + (j & 7) * 2;
        *(uint2*)(wb + off) = make_uint2(hp0, hp1);
    }
    dsum += __shfl_xor_sync(0xffffffffu, dsum, 1);
    dsum += __shfl_xor_sync(0xffffffffu, dsum, 2);
    if (q == 0) sden[wrow * 4 + h] += dsum;
}

__device__ __forceinline__ void mma_head(uint32_t Sb, int slot, float (*acc)[4],
                                         int arow, int brow0, int brow1,
                                         int lane) {
    const uint32_t aBase = Sb + WB_OFF + slot * 16384 + arow * 256;
    const uint32_t b0row = Sb + BB_OFF + slot * 16384 + brow0 * 256;
    const uint32_t b1row = Sb + BB_OFF + slot * 16384 + brow1 * 256;
    const int alow = arow & 7, bl0 = brow0 & 7, bl1 = brow1 & 7;
#pragma unroll
    for (int ks = 0; ks < 8; ks++) {
        uint32_t a4[4], bA[4], bB[4];
        int ach = ks * 2 + (lane >> 4);
        ldm_x4(a4, aBase + ((ach ^ alow) << 4));
        int bch = ks * 2 + ((lane >> 3) & 1);
        ldm_x4(bA, b0row + ((bch ^ bl0) << 4));
        ldm_x4(bB, b1row + ((bch ^ bl1) << 4));
        mma_f16(acc[0], a4, bA);
        mma_f16(acc[1], a4, bA + 2);
        mma_f16(acc[2], a4, bB);
        mma_f16(acc[3], a4, bB + 2);
    }
}

// ---------------- Kernel T: pipelined fused attention -----------------------
__global__ void __launch_bounds__(256, 2) k_attn_mma() {
    extern __shared__ char Sp[];
    const uint32_t Sb = smem_u32(Sp);
    const int t = threadIdx.x, lane = t & 31, wid = t >> 5;
    const int i0 = blockIdx.x * 64;
    const int split = blockIdx.y;

    float2* shEsEa = (float2*)(Sp + ESEA_OFF);
    float*  sden   = (float*)(Sp + DEN_OFF);
    {
        int h = t >> 6, r = t & 63;
        shEsEa[h * 64 + r] = make_float2(g_Es[(size_t)(i0 + r) * NHEAD + h],
                                         g_Eas[(size_t)(i0 + r) * NHEAD + h]);
        sden[t] = 0.0f;
    }

    float acc[NHEAD][4][4];
#pragma unroll
    for (int h = 0; h < NHEAD; h++)
#pragma unroll
        for (int n = 0; n < 4; n++)
#pragma unroll
            for (int k = 0; k < 4; k++) acc[h][n][k] = 0.0f;

    const int q = lane & 3, wrow = wid * 8 + (lane >> 2);
    const int mi = wid & 3, nj = wid >> 2;
    const int arow = mi * 16 + (lane & 15);
    const int brow0 = nj * 32 + (lane & 7) + ((lane >> 4) << 3);
    const int brow1 = brow0 + 16;

    int s0 = 0, s1 = 1, s2 = 2;
    const int jbase = split * JCHUNK;

    // prologue: B(head0, tile0) + meta(tile0)
    load_B_tile(Sb, s0, 0, jbase, t);
    load_meta(Sp, i0, jbase, t);

    for (int jt = 0; jt < JCHUNK / 128; jt++) {
        const int j0 = jbase + jt * 128;
        __syncthreads();                               // meta + bbuf visible
        // W0: wgen(0) | prefetch B1 | ensure B0 done
        load_B_tile(Sb, s1, 1, j0, t);
        wgen_head(Sp, s0, 0, wrow, q);
        CP_WAIT(1);
        __syncthreads();
        // W1: mma(0) | wgen(1) | prefetch B2
        load_B_tile(Sb, s2, 2, j0, t);
        mma_head(Sb, s0, acc[0], arow, brow0, brow1, lane);
        wgen_head(Sp, s1, 1, wrow, q);
        CP_WAIT(1);
        __syncthreads();
        // W2: mma(1) | wgen(2) | prefetch B3
        load_B_tile(Sb, s0, 3, j0, t);
        mma_head(Sb, s1, acc[1], arow, brow0, brow1, lane);
        wgen_head(Sp, s2, 2, wrow, q);
        CP_WAIT(1);
        __syncthreads();
        // W3: mma(2) | wgen(3) | drain
        mma_head(Sb, s2, acc[2], arow, brow0, brow1, lane);
        wgen_head(Sp, s0, 3, wrow, q);
        CP_WAIT(0);
        __syncthreads();
        // W4: mma(3) | next tile's B0 + meta
        mma_head(Sb, s0, acc[3], arow, brow0, brow1, lane);
        if (jt < JCHUNK / 128 - 1) {
            load_B_tile(Sb, s1, 0, j0 + 128, t);
            load_meta(Sp, i0, j0 + 128, t);
        }
        int tmp = s0; s0 = s1; s1 = s2; s2 = tmp;     // rotate slots
    }
    __syncthreads();

    // epilogue: write partial num / den
    {
        const int r1 = mi * 16 + (lane >> 2), r2 = r1 + 8;
        const int cb = nj * 32 + (lane & 3) * 2;
#pragma unroll
        for (int h = 0; h < NHEAD; h++)
#pragma unroll
            for (int nt = 0; nt < 4; nt++) {
                int c = h * CHEAD + nt * 8 + cb;
                size_t o1 = ((size_t)split * NN + i0 + r1) * COUT + c;
                size_t o2 = ((size_t)split * NN + i0 + r2) * COUT + c;
                *(float2*)&g_pnum[o1] = make_float2(acc[h][nt][0], acc[h][nt][1]);
                *(float2*)&g_pnum[o2] = make_float2(acc[h][nt][2], acc[h][nt][3]);
            }
        g_pden[((size_t)split * NN + i0 + (t >> 2)) * NHEAD + (t & 3)] = sden[t];
    }
}

// ---------------- Kernel F: combine splits + normalize ----------------------
__global__ __launch_bounds__(256) void k_final(float* __restrict__ out) {
    int gid = blockIdx.x * 256 + threadIdx.x;
    int node = gid >> 8, col = gid & 255, h = col >> 6;
    float num = 0.0f, den = 0.0f;
#pragma unroll
    for (int s = 0; s < NSPLIT; s++) {
        num += g_pnum[((size_t)s * NN + node) * COUT + col];
        den += g_pden[((size_t)s * NN + node) * NHEAD + h];
    }
    out[gid] = num / den;
}

// ---------------- Launch -----------------------------------------------------
extern "C" void kernel_launch(void* const* d_in, const int* in_sizes, int n_in,
                              void* d_out, int out_size) {
    const float* X   = (const float*)d_in[0];
    const int*   adj = (const int*)d_in[1];
    const float* W   = (const float*)d_in[2];
    const float* b   = (const float*)d_in[3];
    const float* a   = (const float*)d_in[4];
    float* out = (float*)d_out;

    cudaFuncSetAttribute(k_attn_mma, cudaFuncAttributeMaxDynamicSharedMemorySize,
                         SMEM_DYN);

    k_gemm_h<<<dim3(64, 4), 256>>>(X, W, b);
    k_pack<<<NN * (NN / 32) / 256, 256>>>(adj);
    k_edge<<<128, 128>>>(a);
    k_prep<<<dim3(NN / 32, COUT / 32), dim3(32, 8)>>>();
    k_attn_mma<<<dim3(NN / 64, NSPLIT), 256, SMEM_DYN>>>();
    k_final<<<NN * COUT / 256, 256>>>(out);
}